// round 16
// baseline (speedup 1.0000x reference)
#include <cuda_runtime.h>
#include <cuda_bf16.h>
#include <cuda_fp16.h>
#include <math.h>
#include <stdint.h>

// ---------------- problem constants ----------------
#define V_   32000
#define D_   1024
#define H_   16
#define KVH_ 4
#define HD_  64
#define F_   4096
#define L_   2
#define B_   2
#define S_   2048
#define T_   (B_*S_)
#define REP_ (H_/KVH_)
#define EPS_ 1e-5f
#define SCALE_ 0.125f
#define QKV_ 1536            // fused q|k|v width
#define GU_  8192            // fused gate|up width (interleaved: even=gate, odd=up)

typedef __half fp16;

// ---------------- scratch ----------------
__device__ float g_x  [T_*D_];
__device__ float g_qkv[T_*QKV_];
__device__ int   g_is64;

// activation fp16 planes
__device__ fp16 g_nH [T_*D_];                       // norm out, 1-plane
__device__ fp16 g_qH [T_*D_];                       // q, 1-plane (scaled)
__device__ fp16 g_kh [T_*KVH_*HD_], g_kl [T_*KVH_*HD_];  // k, 2-plane
__device__ fp16 g_vh [T_*KVH_*HD_], g_vl [T_*KVH_*HD_];  // v, 2-plane
__device__ fp16 g_cH [T_*D_];                       // ctx, 1-plane
__device__ fp16 g_gH [T_*F_];                       // silu out, 1-plane

// weight planes, [K, N] layout, fp16 2-plane, fused along N
__device__ fp16 g_wqkvH_h[L_*D_*QKV_], g_wqkvH_l[L_*D_*QKV_];
__device__ fp16 g_woH_h  [L_*D_*D_],   g_woH_l  [L_*D_*D_];
__device__ fp16 g_wguH_h [L_*D_*GU_],  g_wguH_l [L_*D_*GU_];   // interleaved g/u
__device__ fp16 g_wdH_h  [L_*F_*D_],   g_wdH_l  [L_*F_*D_];
__device__ fp16 g_woutH_h[D_*V_],      g_woutH_l[D_*V_];

// ---------------- helpers ----------------
__device__ __forceinline__ uint32_t pack2h(fp16 a, fp16 b) {
    __half2 t = __halves2half2(a, b);
    return *reinterpret_cast<uint32_t*>(&t);
}
__device__ __forceinline__ void split1h(float v, fp16& h, fp16& l) {
    h = __float2half(v);
    l = __float2half(v - __half2float(h));
}

#define LDSM4(r, addr) \
    asm volatile("ldmatrix.sync.aligned.m8n8.x4.shared.b16 {%0,%1,%2,%3}, [%4];" \
        : "=r"((r)[0]), "=r"((r)[1]), "=r"((r)[2]), "=r"((r)[3]) : "r"(addr))
#define LDSM4T(r, addr) \
    asm volatile("ldmatrix.sync.aligned.m8n8.x4.trans.shared.b16 {%0,%1,%2,%3}, [%4];" \
        : "=r"((r)[0]), "=r"((r)[1]), "=r"((r)[2]), "=r"((r)[3]) : "r"(addr))
#define MMA_F16(acc, a, b0, b1) \
    asm volatile("mma.sync.aligned.m16n8k16.row.col.f32.f16.f16.f32 " \
        "{%0,%1,%2,%3}, {%4,%5,%6,%7}, {%8,%9}, {%0,%1,%2,%3};" \
        : "+f"((acc)[0]), "+f"((acc)[1]), "+f"((acc)[2]), "+f"((acc)[3]) \
        : "r"((a)[0]), "r"((a)[1]), "r"((a)[2]), "r"((a)[3]), "r"(b0), "r"(b1))
#define CP16(dst, src) \
    asm volatile("cp.async.cg.shared.global [%0], [%1], 16;\n" :: "r"(dst), "l"(src) : "memory")
#define CP_COMMIT() asm volatile("cp.async.commit_group;\n" ::: "memory")
#define CP_WAIT(n)  asm volatile("cp.async.wait_group %0;\n" :: "n"(n) : "memory")

// ---------------- fp32 -> fp16 hi/lo split ----------------
__global__ void splith_kernel(const float* __restrict__ in,
                              fp16* __restrict__ hi, fp16* __restrict__ lo, int n4) {
    int i = blockIdx.x * blockDim.x + threadIdx.x;
    if (i >= n4) return;
    float4 v = ((const float4*)in)[i];
    float vv[4] = {v.x, v.y, v.z, v.w};
    fp16 h[4], l[4];
    #pragma unroll
    for (int j = 0; j < 4; j++) split1h(vv[j], h[j], l[j]);
    ((uint2*)hi)[i] = make_uint2(pack2h(h[0],h[1]), pack2h(h[2],h[3]));
    ((uint2*)lo)[i] = make_uint2(pack2h(l[0],l[1]), pack2h(l[2],l[3]));
}

// ---- strided fp16 split: in[K,Nin] -> planes[K,Nout] at column cOff ----
__global__ void splitwh_kernel(const float* __restrict__ in,
                               fp16* __restrict__ oh, fp16* __restrict__ ol,
                               int Nin, int Nout, int cOff, int n4) {
    int i = blockIdx.x * blockDim.x + threadIdx.x;
    if (i >= n4) return;
    int rc4 = Nin >> 2;
    int r = i / rc4, c4 = i - r * rc4;
    float4 v = ((const float4*)in)[i];
    float vv[4] = {v.x, v.y, v.z, v.w};
    fp16 h[4], l[4];
    #pragma unroll
    for (int q = 0; q < 4; q++) split1h(vv[q], h[q], l[q]);
    size_t oi = ((size_t)r * Nout + cOff) / 4 + c4;
    ((uint2*)oh)[oi] = make_uint2(pack2h(h[0],h[1]), pack2h(h[2],h[3]));
    ((uint2*)ol)[oi] = make_uint2(pack2h(l[0],l[1]), pack2h(l[2],l[3]));
}

// ---- gate/up interleaved fp16 split ----
__global__ void splitguh_kernel(const float* __restrict__ wg,
                                const float* __restrict__ wu,
                                fp16* __restrict__ oh, fp16* __restrict__ ol, int n4) {
    int i = blockIdx.x * blockDim.x + threadIdx.x;
    if (i >= n4) return;
    float4 gv = ((const float4*)wg)[i];
    float4 uv = ((const float4*)wu)[i];
    float gg[4] = {gv.x, gv.y, gv.z, gv.w};
    float uu[4] = {uv.x, uv.y, uv.z, uv.w};
    fp16 ghh[4], gll[4], uhh[4], ull[4];
    #pragma unroll
    for (int q = 0; q < 4; q++) { split1h(gg[q], ghh[q], gll[q]); split1h(uu[q], uhh[q], ull[q]); }
    uint4 hO, lO;
    hO.x = pack2h(ghh[0], uhh[0]); hO.y = pack2h(ghh[1], uhh[1]);
    hO.z = pack2h(ghh[2], uhh[2]); hO.w = pack2h(ghh[3], uhh[3]);
    lO.x = pack2h(gll[0], ull[0]); lO.y = pack2h(gll[1], ull[1]);
    lO.z = pack2h(gll[2], ull[2]); lO.w = pack2h(gll[3], ull[3]);
    ((uint4*)oh)[i] = hO;
    ((uint4*)ol)[i] = lO;
}

// ---------------- idx detection + embed ----------------
__global__ void detect_idx_kernel(const int* idx) {
    __shared__ int ok;
    if (threadIdx.x == 0) ok = 1;
    __syncthreads();
    int bad = 0;
    for (int i = threadIdx.x; i < T_/2; i += blockDim.x)
        if (idx[2*i + 1] != 0) bad = 1;
    if (bad) atomicAnd(&ok, 0);
    __syncthreads();
    if (threadIdx.x == 0) g_is64 = ok;
}
__global__ void embed_kernel(const void* idx, const float* __restrict__ emb) {
    int t = blockIdx.x;
    int tok = g_is64 ? (int)((const long long*)idx)[t] : ((const int*)idx)[t];
    ((float4*)(g_x + (size_t)t * D_))[threadIdx.x] =
        ((const float4*)(emb + (size_t)tok * D_))[threadIdx.x];
}

// ---------------- RMSNorm -> fp16 single plane --------------------------
__global__ void rmsnorm_h_kernel(const float* __restrict__ x,
                                 const float* __restrict__ w,
                                 fp16* __restrict__ o) {
    int t = blockIdx.x;
    __shared__ float red[8];
    float4 v = ((const float4*)(x + (size_t)t * D_))[threadIdx.x];
    float ss = v.x*v.x + v.y*v.y + v.z*v.z + v.w*v.w;
    #pragma unroll
    for (int off = 16; off > 0; off >>= 1) ss += __shfl_xor_sync(0xffffffffu, ss, off);
    if ((threadIdx.x & 31) == 0) red[threadIdx.x >> 5] = ss;
    __syncthreads();
    if (threadIdx.x < 8) {
        float s = red[threadIdx.x];
        #pragma unroll
        for (int off = 4; off > 0; off >>= 1) s += __shfl_xor_sync(0xffu, s, off);
        if (threadIdx.x == 0) red[0] = s;
    }
    __syncthreads();
    float inv = rsqrtf(red[0] * (1.0f / D_) + EPS_);
    float4 wv = ((const float4*)w)[threadIdx.x];
    fp16 h0 = __float2half(v.x*inv*wv.x), h1 = __float2half(v.y*inv*wv.y);
    fp16 h2 = __float2half(v.z*inv*wv.z), h3 = __float2half(v.w*inv*wv.w);
    ((uint2*)(o + (size_t)t*D_))[threadIdx.x] = make_uint2(pack2h(h0,h1), pack2h(h2,h3));
}

// ------- merged qkv postprocess: rope(q), rope(k 2-plane), v split ------
// grid = T_, block = 512.
__global__ void __launch_bounds__(512)
qkvpost_kernel(const float* __restrict__ x,
               fp16* __restrict__ q,
               fp16* __restrict__ kh, fp16* __restrict__ kl,
               fp16* __restrict__ vh, fp16* __restrict__ vl) {
    int t   = blockIdx.x;
    int pos = t % S_;
    int tid = threadIdx.x;
    int j   = tid & 31;
    int h   = tid >> 5;          // 0..15
    float invf = powf(500000.0f, -(float)(2 * j) / (float)HD_);
    float ang = (float)pos * invf;
    float s, c;
    sincosf(ang, &s, &c);

    // q: all 16 heads
    {
        const float* p = x + (size_t)t * QKV_ + h * HD_;
        size_t ob = (size_t)t * D_ + h * HD_;
        float a = p[j], b = p[j + 32];
        q[ob + j]      = __float2half((a * c - b * s) * SCALE_);
        q[ob + j + 32] = __float2half((b * c + a * s) * SCALE_);
    }
    // k: heads 0..3 handled by tid < 128
    if (tid < 128) {
        const float* p = x + (size_t)t * QKV_ + 1024 + h * HD_;
        size_t ob = (size_t)t * (KVH_*HD_) + h * HD_;
        float a = p[j], b = p[j + 32];
        float r0 = a * c - b * s;
        float r1 = b * c + a * s;
        fp16 h0, l0, h1, l1;
        split1h(r0, h0, l0); split1h(r1, h1, l1);
        kh[ob + j] = h0;       kl[ob + j] = l0;
        kh[ob + j + 32] = h1;  kl[ob + j + 32] = l1;
    }
    // v: 256 floats, tid < 64 each does float4
    if (tid < 64) {
        float4 v = *(const float4*)(x + (size_t)t*QKV_ + 1280 + tid*4);
        float vv[4] = {v.x, v.y, v.z, v.w};
        fp16 hh[4], ll[4];
        #pragma unroll
        for (int jq = 0; jq < 4; jq++) split1h(vv[jq], hh[jq], ll[jq]);
        ((uint2*)(vh + (size_t)t*256))[tid] = make_uint2(pack2h(hh[0],hh[1]), pack2h(hh[2],hh[3]));
        ((uint2*)(vl + (size_t)t*256))[tid] = make_uint2(pack2h(ll[0],ll[1]), pack2h(ll[2],ll[3]));
    }
}

// ======== fp16 2-MMA GEMM: A 1-plane, B 2-plane =========================
// Grid: (M/BM, N/BN) — M fastest-varying so all M-tiles of one B tile run
// concurrently and share B through L2 (B can exceed L2; A never does).
// EPI 0: fp32 out (+opt Res).  EPI 1: silu(gate)*up from interleaved cols,
//        fp16 1-plane out of width N/2.
#define BM_  128
#define BN_  128
#define BKK_ 32
#define AST_ 40
#define BST_ 136
#define ASZ_ (BM_*AST_)
#define BSZ_ (BKK_*BST_)
#define HG_SMEM ((2*ASZ_ + 2*BSZ_*2) * 2)

template <int EPI>
__global__ void __launch_bounds__(256)
hgemm_kernel(const fp16* __restrict__ Ag,
             const fp16* __restrict__ Bhg, const fp16* __restrict__ Blg,
             const float* __restrict__ Res, float* __restrict__ C,
             fp16* __restrict__ O, int M, int N, int K) {
    extern __shared__ fp16 hsm[];
    fp16* sA  = hsm;
    fp16* sBh = sA + 2*ASZ_;
    fp16* sBl = sBh + 2*BSZ_;

    const int tid  = threadIdx.x;
    const int lane = tid & 31, warp = tid >> 5;
    const int warpM = warp >> 1, warpN = warp & 1;
    const int by = blockIdx.x;   // M-tile: fastest-varying (L2 B-sharing)
    const int bx = blockIdx.y;   // N-tile

    const fp16* Ab  = Ag  + (size_t)by * BM_ * K;
    const fp16* Bhb = Bhg + (size_t)bx * BN_;
    const fp16* Blb = Blg + (size_t)bx * BN_;

    const uint32_t uA  = (uint32_t)__cvta_generic_to_shared(sA);
    const uint32_t uBh = (uint32_t)__cvta_generic_to_shared(sBh);
    const uint32_t uBl = (uint32_t)__cvta_generic_to_shared(sBl);

    const int ar = tid >> 2, ac = (tid & 3) * 8;
    const int br = tid >> 4, bc = (tid & 15) * 8;

    auto load_stage = [&](int st, int k0) {
        #pragma unroll
        for (int p = 0; p < 2; p++) {
            int r = ar + p*64;
            uint32_t d = (uint32_t)((st*ASZ_ + r*AST_ + ac) * 2);
            CP16(uA + d, Ab + (size_t)r*K + k0 + ac);
        }
        #pragma unroll
        for (int p = 0; p < 2; p++) {
            int r = br + p*16;
            uint32_t d = (uint32_t)((st*BSZ_ + r*BST_ + bc) * 2);
            CP16(uBh + d, Bhb + (size_t)(k0 + r)*N + bc);
            CP16(uBl + d, Blb + (size_t)(k0 + r)*N + bc);
        }
    };

    float acc[2][8][4];
    #pragma unroll
    for (int i = 0; i < 2; i++)
        #pragma unroll
        for (int j = 0; j < 8; j++)
            #pragma unroll
            for (int q = 0; q < 4; q++) acc[i][j][q] = 0.f;

    const int arow = warpM*32 + (lane & 15);
    const int acol = (lane >> 4) * 8;
    const int brow = (lane & 15);
    const int bcol = warpN*64 + (lane >> 4) * 8;

    const int kIters = K / BKK_;
    load_stage(0, 0);
    CP_COMMIT();

    for (int it = 0; it < kIters; ++it) {
        if (it + 1 < kIters) {
            load_stage((it+1)&1, (it+1)*BKK_);
            CP_COMMIT();
            CP_WAIT(1);
        } else {
            CP_WAIT(0);
        }
        __syncthreads();
        const int st = it & 1;
        const uint32_t aA = uA  + (uint32_t)(st*ASZ_*2);
        const uint32_t bH = uBh + (uint32_t)(st*BSZ_*2);
        const uint32_t bL = uBl + (uint32_t)(st*BSZ_*2);
        #pragma unroll
        for (int kk = 0; kk < BKK_; kk += 16) {
            uint32_t a4[2][4];
            #pragma unroll
            for (int mt = 0; mt < 2; mt++) {
                uint32_t off = (uint32_t)(((arow + mt*16)*AST_ + kk + acol) * 2);
                LDSM4(a4[mt], aA + off);
            }
            #pragma unroll
            for (int pr = 0; pr < 4; pr++) {
                uint32_t off = (uint32_t)(((brow + kk)*BST_ + bcol + pr*16) * 2);
                uint32_t bh[4], bl[4];
                LDSM4T(bh, bH + off);
                LDSM4T(bl, bL + off);
                #pragma unroll
                for (int mt = 0; mt < 2; mt++) {
                    #pragma unroll
                    for (int h2 = 0; h2 < 2; h2++) {
                        int nt = pr*2 + h2;
                        MMA_F16(acc[mt][nt], a4[mt], bh[h2*2], bh[h2*2+1]);
                        MMA_F16(acc[mt][nt], a4[mt], bl[h2*2], bl[h2*2+1]);
                    }
                }
            }
        }
        __syncthreads();
    }

    const int g = lane >> 2, tg = lane & 3;
    if (EPI == 0) {
        #pragma unroll
        for (int mt = 0; mt < 2; mt++) {
            #pragma unroll
            for (int nt = 0; nt < 8; nt++) {
                size_t r0 = (size_t)by*BM_ + warpM*32 + mt*16 + g;
                size_t c  = (size_t)bx*BN_ + warpN*64 + nt*8 + tg*2;
                float2 v0 = make_float2(acc[mt][nt][0], acc[mt][nt][1]);
                float2 v1 = make_float2(acc[mt][nt][2], acc[mt][nt][3]);
                if (Res) {
                    float2 q0 = *(const float2*)(Res + r0*N + c);
                    float2 q1 = *(const float2*)(Res + (r0+8)*N + c);
                    v0.x += q0.x; v0.y += q0.y; v1.x += q1.x; v1.y += q1.y;
                }
                *(float2*)(C + r0*N + c)     = v0;
                *(float2*)(C + (r0+8)*N + c) = v1;
            }
        }
    } else {
        // silu(gate)*up epilogue: cols (c, c+1) = (gate_j, up_j), j = c/2.
        const int NO = N >> 1;
        #pragma unroll
        for (int mt = 0; mt < 2; mt++) {
            #pragma unroll
            for (int nt = 0; nt < 8; nt++) {
                size_t r0 = (size_t)by*BM_ + warpM*32 + mt*16 + g;
                size_t j  = (size_t)bx*(BN_/2) + warpN*32 + nt*4 + tg;
                float gate0 = acc[mt][nt][0], up0 = acc[mt][nt][1];
                float gate1 = acc[mt][nt][2], up1 = acc[mt][nt][3];
                float v0 = gate0 / (1.f + __expf(-gate0)) * up0;
                float v1 = gate1 / (1.f + __expf(-gate1)) * up1;
                O[r0*NO + j]     = __float2half(v0);
                O[(r0+8)*NO + j] = __float2half(v1);
            }
        }
    }
}

// ================= fp16 flash attention (2-MMA) =========================
// Q 1-plane (pre-scaled), K/V 2-plane, P 1-plane, ctx 1-plane out.
#define FST 72
#define FQSZ (64*FST)
#define FL_SMEM (5 * FQSZ * 2)

__global__ void __launch_bounds__(128)
flash_h_kernel(const fp16* __restrict__ qg,
               const fp16* __restrict__ kh, const fp16* __restrict__ kl,
               const fp16* __restrict__ vh, const fp16* __restrict__ vl,
               fp16* __restrict__ cg) {
    extern __shared__ fp16 fsm[];
    fp16* sQ  = fsm;
    fp16* sKh = sQ  + FQSZ;
    fp16* sKl = sKh + FQSZ;
    fp16* sVh = sKl + FQSZ;
    fp16* sVl = sVh + FQSZ;

    const int q0  = blockIdx.x * 64;
    const int h   = blockIdx.y;
    const int b   = blockIdx.z;
    const int kvh = h / REP_;
    const int tid = threadIdx.x;
    const int lane = tid & 31, warp = tid >> 5;
    const int g = lane >> 2, tg = lane & 3;

    for (int li = tid; li < 512; li += 128) {
        int r = li >> 3, c8 = (li & 7) * 8;
        size_t src = ((size_t)(b * S_ + q0 + r) * D_ + h * HD_ + c8);
        *(uint4*)&sQ[r*FST + c8] = *(const uint4*)(qg + src);
    }

    float mrow[2] = {-INFINITY, -INFINITY};
    float lrow[2] = {0.f, 0.f};
    float o[8][4] = {};

    const uint32_t uQ  = (uint32_t)__cvta_generic_to_shared(sQ);
    const uint32_t uKh = (uint32_t)__cvta_generic_to_shared(sKh);
    const uint32_t uKl = (uint32_t)__cvta_generic_to_shared(sKl);
    const uint32_t uVh = (uint32_t)__cvta_generic_to_shared(sVh);
    const uint32_t uVl = (uint32_t)__cvta_generic_to_shared(sVl);
    const int fr = (lane & 15);
    const int fc = (lane >> 4) * 8;

    const int ntiles = q0 / 64 + 1;
    for (int tI = 0; tI < ntiles; tI++) {
        int kv0 = tI * 64;
        __syncthreads();
        for (int li = tid; li < 512; li += 128) {
            int r = li >> 3, c8 = (li & 7) * 8;
            size_t src = ((size_t)(b * S_ + kv0 + r) * (KVH_*HD_) + kvh * HD_ + c8);
            *(uint4*)&sKh[r*FST + c8] = *(const uint4*)(kh + src);
            *(uint4*)&sKl[r*FST + c8] = *(const uint4*)(kl + src);
            *(uint4*)&sVh[r*FST + c8] = *(const uint4*)(vh + src);
            *(uint4*)&sVl[r*FST + c8] = *(const uint4*)(vl + src);
        }
        __syncthreads();

        // S = Q K^T : 2 MMAs (q·kh + q·kl)
        float s[8][4] = {};
        #pragma unroll
        for (int kk = 0; kk < 64; kk += 16) {
            uint32_t aq[4];
            uint32_t qoff = (uint32_t)(((warp*16 + fr)*FST + kk + fc) * 2);
            LDSM4(aq, uQ + qoff);
            #pragma unroll
            for (int nb = 0; nb < 4; nb++) {
                uint32_t koff = (uint32_t)(((nb*16 + fr)*FST + kk + fc) * 2);
                uint32_t k4h[4], k4l[4];
                LDSM4(k4h, uKh + koff);
                LDSM4(k4l, uKl + koff);
                MMA_F16(s[nb*2],   aq, k4h[0], k4h[2]);
                MMA_F16(s[nb*2],   aq, k4l[0], k4l[2]);
                MMA_F16(s[nb*2+1], aq, k4h[1], k4h[3]);
                MMA_F16(s[nb*2+1], aq, k4l[1], k4l[3]);
            }
        }

        if (tI == ntiles - 1) {
            #pragma unroll
            for (int nt = 0; nt < 8; nt++) {
                int col = kv0 + nt*8 + tg*2;
                int r0g = q0 + warp*16 + g;
                if (col     > r0g)   s[nt][0] = -INFINITY;
                if (col + 1 > r0g)   s[nt][1] = -INFINITY;
                if (col     > r0g+8) s[nt][2] = -INFINITY;
                if (col + 1 > r0g+8) s[nt][3] = -INFINITY;
            }
        }

        #pragma unroll
        for (int qi = 0; qi < 2; qi++) {
            float mx = -INFINITY;
            #pragma unroll
            for (int nt = 0; nt < 8; nt++)
                mx = fmaxf(mx, fmaxf(s[nt][qi*2], s[nt][qi*2+1]));
            mx = fmaxf(mx, __shfl_xor_sync(0xffffffffu, mx, 1));
            mx = fmaxf(mx, __shfl_xor_sync(0xffffffffu, mx, 2));
            float mnew = fmaxf(mrow[qi], mx);
            float scale = __expf(mrow[qi] - mnew);
            mrow[qi] = mnew;
            float sum = 0.f;
            #pragma unroll
            for (int nt = 0; nt < 8; nt++) {
                float p0 = __expf(s[nt][qi*2]   - mnew);
                float p1 = __expf(s[nt][qi*2+1] - mnew);
                s[nt][qi*2] = p0; s[nt][qi*2+1] = p1;
                sum += p0 + p1;
            }
            sum += __shfl_xor_sync(0xffffffffu, sum, 1);
            sum += __shfl_xor_sync(0xffffffffu, sum, 2);
            lrow[qi] = lrow[qi]*scale + sum;
            #pragma unroll
            for (int nt = 0; nt < 8; nt++) {
                o[nt][qi*2]   *= scale;
                o[nt][qi*2+1] *= scale;
            }
        }

        // O += P V : 2 MMAs (p·vh + p·vl); P packed fp16 1-plane
        #pragma unroll
        for (int ks = 0; ks < 4; ks++) {
            const float* s0 = s[2*ks];
            const float* s1 = s[2*ks+1];
            uint32_t ph[4];
            ph[0] = pack2h(__float2half(s0[0]), __float2half(s0[1]));
            ph[1] = pack2h(__float2half(s0[2]), __float2half(s0[3]));
            ph[2] = pack2h(__float2half(s1[0]), __float2half(s1[1]));
            ph[3] = pack2h(__float2half(s1[2]), __float2half(s1[3]));
            #pragma unroll
            for (int nb = 0; nb < 4; nb++) {
                uint32_t voff = (uint32_t)(((ks*16 + fr)*FST + nb*16 + fc) * 2);
                uint32_t v4h[4], v4l[4];
                LDSM4T(v4h, uVh + voff);
                LDSM4T(v4l, uVl + voff);
                MMA_F16(o[nb*2],   ph, v4h[0], v4h[1]);
                MMA_F16(o[nb*2],   ph, v4l[0], v4l[1]);
                MMA_F16(o[nb*2+1], ph, v4h[2], v4h[3]);
                MMA_F16(o[nb*2+1], ph, v4l[2], v4l[3]);
            }
        }
    }

    #pragma unroll
    for (int qi = 0; qi < 2; qi++) {
        float inv = 1.0f / lrow[qi];
        int r = q0 + warp*16 + g + qi*8;
        size_t base = (size_t)(b * S_ + r) * D_ + h * HD_;
        #pragma unroll
        for (int nt = 0; nt < 8; nt++) {
            int c = nt*8 + tg*2;
            *(uint32_t*)(cg + base + c) =
                pack2h(__float2half(o[nt][qi*2] * inv),
                       __float2half(o[nt][qi*2+1] * inv));
        }
    }
}

// ---------------- host orchestration ----------------
extern "C" void kernel_launch(void* const* d_in, const int* in_sizes, int n_in,
                              void* d_out, int out_size) {
    const void*  idx    = d_in[0];
    const float* emb    = (const float*)d_in[1];
    const float* wq     = (const float*)d_in[2];
    const float* wk     = (const float*)d_in[3];
    const float* wv     = (const float*)d_in[4];
    const float* wo     = (const float*)d_in[5];
    const float* wgate  = (const float*)d_in[6];
    const float* wup    = (const float*)d_in[7];
    const float* wdown  = (const float*)d_in[8];
    const float* na     = (const float*)d_in[9];
    const float* nf     = (const float*)d_in[10];
    const float* nfin   = (const float*)d_in[11];
    const float* wout   = (const float*)d_in[12];

    float *x, *qkv;
    cudaGetSymbolAddress((void**)&x,   g_x);
    cudaGetSymbolAddress((void**)&qkv, g_qkv);

    fp16 *nH, *qH, *kh, *kl, *vh, *vl, *cH, *gH;
    cudaGetSymbolAddress((void**)&nH, g_nH);
    cudaGetSymbolAddress((void**)&qH, g_qH);
    cudaGetSymbolAddress((void**)&kh, g_kh); cudaGetSymbolAddress((void**)&kl, g_kl);
    cudaGetSymbolAddress((void**)&vh, g_vh); cudaGetSymbolAddress((void**)&vl, g_vl);
    cudaGetSymbolAddress((void**)&cH, g_cH);
    cudaGetSymbolAddress((void**)&gH, g_gH);

    fp16 *wqkvH_h,*wqkvH_l,*woH_h,*woH_l,*wguH_h,*wguH_l,*wdH_h,*wdH_l,*woutH_h,*woutH_l;
    cudaGetSymbolAddress((void**)&wqkvH_h, g_wqkvH_h); cudaGetSymbolAddress((void**)&wqkvH_l, g_wqkvH_l);
    cudaGetSymbolAddress((void**)&woH_h,  g_woH_h);   cudaGetSymbolAddress((void**)&woH_l,  g_woH_l);
    cudaGetSymbolAddress((void**)&wguH_h, g_wguH_h);  cudaGetSymbolAddress((void**)&wguH_l, g_wguH_l);
    cudaGetSymbolAddress((void**)&wdH_h,  g_wdH_h);   cudaGetSymbolAddress((void**)&wdH_l,  g_wdH_l);
    cudaGetSymbolAddress((void**)&woutH_h,g_woutH_h); cudaGetSymbolAddress((void**)&woutH_l,g_woutH_l);

    cudaFuncSetAttribute(hgemm_kernel<0>,
                         cudaFuncAttributeMaxDynamicSharedMemorySize, HG_SMEM);
    cudaFuncSetAttribute(hgemm_kernel<1>,
                         cudaFuncAttributeMaxDynamicSharedMemorySize, HG_SMEM);
    cudaFuncSetAttribute(flash_h_kernel,
                         cudaFuncAttributeMaxDynamicSharedMemorySize, FL_SMEM);

    // weight splits (all fp16 2-plane)
    for (int l = 0; l < L_; l++) {
        size_t qo = (size_t)l * D_ * QKV_;
        {
            int n4 = D_ * D_ / 4;
            splitwh_kernel<<<(n4 + 255) / 256, 256>>>(
                wq + (size_t)l*D_*D_, wqkvH_h + qo, wqkvH_l + qo, D_, QKV_, 0, n4);
        }
        {
            int n4 = D_ * 256 / 4;
            splitwh_kernel<<<(n4 + 255) / 256, 256>>>(
                wk + (size_t)l*D_*256, wqkvH_h + qo, wqkvH_l + qo, 256, QKV_, 1024, n4);
            splitwh_kernel<<<(n4 + 255) / 256, 256>>>(
                wv + (size_t)l*D_*256, wqkvH_h + qo, wqkvH_l + qo, 256, QKV_, 1280, n4);
        }
        {
            int n4 = D_ * D_ / 4;
            splith_kernel<<<(n4 + 255) / 256, 256>>>(
                wo + (size_t)l*D_*D_, woH_h + (size_t)l*D_*D_, woH_l + (size_t)l*D_*D_, n4);
        }
        size_t go = (size_t)l * D_ * GU_;
        {
            int n4 = D_ * F_ / 4;
            splitguh_kernel<<<(n4 + 255) / 256, 256>>>(
                wgate + (size_t)l*D_*F_, wup + (size_t)l*D_*F_,
                wguH_h + go, wguH_l + go, n4);
        }
        {
            int n4 = F_ * D_ / 4;
            splith_kernel<<<(n4 + 255) / 256, 256>>>(
                wdown + (size_t)l*F_*D_, wdH_h + (size_t)l*F_*D_,
                wdH_l + (size_t)l*F_*D_, n4);
        }
    }
    {
        int n4 = (int)((size_t)D_*V_/4);
        splith_kernel<<<(n4 + 255) / 256, 256>>>(wout, woutH_h, woutH_l, n4);
    }

    detect_idx_kernel<<<1, 256>>>((const int*)idx);
    embed_kernel<<<T_, 256>>>(idx, emb);

    for (int l = 0; l < L_; l++) {
        size_t qo = (size_t)l * D_ * QKV_;
        size_t go = (size_t)l * D_ * GU_;
        rmsnorm_h_kernel<<<T_, 256>>>(x, na + (size_t)l * D_, nH);
        {   // QKV   (grid: M fastest)
            dim3 grid(T_ / BM_, QKV_ / BN_);
            hgemm_kernel<0><<<grid, 256, HG_SMEM>>>(nH, wqkvH_h + qo, wqkvH_l + qo,
                                                    nullptr, qkv, nullptr, T_, QKV_, D_);
        }
        qkvpost_kernel<<<T_, 512>>>(qkv, qH, kh, kl, vh, vl);
        flash_h_kernel<<<dim3(S_/64, H_, B_), 128, FL_SMEM>>>(qH, kh, kl, vh, vl, cH);
        {   // wo + residual
            dim3 grid(T_ / BM_, D_ / BN_);
            hgemm_kernel<0><<<grid, 256, HG_SMEM>>>(cH, woH_h + (size_t)l*D_*D_,
                                                    woH_l + (size_t)l*D_*D_,
                                                    x, x, nullptr, T_, D_, D_);
        }
        rmsnorm_h_kernel<<<T_, 256>>>(x, nf + (size_t)l * D_, nH);
        {   // GU with fused silu
            dim3 grid(T_ / BM_, GU_ / BN_);
            hgemm_kernel<1><<<grid, 256, HG_SMEM>>>(nH, wguH_h + go, wguH_l + go,
                                                    nullptr, nullptr, gH, T_, GU_, D_);
        }
        {   // wdown + residual
            dim3 grid(T_ / BM_, D_ / BN_);
            hgemm_kernel<0><<<grid, 256, HG_SMEM>>>(gH, wdH_h + (size_t)l*F_*D_,
                                                    wdH_l + (size_t)l*F_*D_,
                                                    x, x, nullptr, T_, D_, F_);
        }
    }

    rmsnorm_h_kernel<<<T_, 256>>>(x, nfin, nH);
    {   // vocab projection (grid: M fastest — the big winner)
        dim3 grid(T_ / BM_, V_ / BN_);
        hgemm_kernel<0><<<grid, 256, HG_SMEM>>>(nH, woutH_h, woutH_l,
                                                nullptr, (float*)d_out, nullptr,
                                                T_, V_, D_);
    }
}

// round 17
// speedup vs baseline: 1.5221x; 1.5221x over previous
#include <cuda_runtime.h>
#include <cuda_bf16.h>
#include <cuda_fp16.h>
#include <math.h>
#include <stdint.h>

// ---------------- problem constants ----------------
#define V_   32000
#define D_   1024
#define H_   16
#define KVH_ 4
#define HD_  64
#define F_   4096
#define L_   2
#define B_   2
#define S_   2048
#define T_   (B_*S_)
#define REP_ (H_/KVH_)
#define EPS_ 1e-5f
#define SCALE_ 0.125f
#define QKV_ 1536            // fused q|k|v width
#define GU_  8192            // fused gate|up width (interleaved: even=gate, odd=up)

typedef __half fp16;

// ---------------- scratch ----------------
__device__ float g_x  [T_*D_];
__device__ float g_qkv[T_*QKV_];
__device__ int   g_is64;

// activation fp16 planes
__device__ fp16 g_nH [T_*D_];                       // norm out, 1-plane
__device__ fp16 g_qH [T_*D_];                       // q, 1-plane (scaled)
__device__ fp16 g_kh [T_*KVH_*HD_], g_kl [T_*KVH_*HD_];  // k, 2-plane
__device__ fp16 g_vh [T_*KVH_*HD_], g_vl [T_*KVH_*HD_];  // v, 2-plane
__device__ fp16 g_cH [T_*D_];                       // ctx, 1-plane
__device__ fp16 g_gH [T_*F_];                       // silu out, 1-plane

// weight planes, [K, N] layout, fp16 2-plane, fused along N
__device__ fp16 g_wqkvH_h[L_*D_*QKV_], g_wqkvH_l[L_*D_*QKV_];
__device__ fp16 g_woH_h  [L_*D_*D_],   g_woH_l  [L_*D_*D_];
__device__ fp16 g_wguH_h [L_*D_*GU_],  g_wguH_l [L_*D_*GU_];   // interleaved g/u
__device__ fp16 g_wdH_h  [L_*F_*D_],   g_wdH_l  [L_*F_*D_];
__device__ fp16 g_woutH_h[D_*V_],      g_woutH_l[D_*V_];

// ---------------- helpers ----------------
__device__ __forceinline__ uint32_t pack2h(fp16 a, fp16 b) {
    __half2 t = __halves2half2(a, b);
    return *reinterpret_cast<uint32_t*>(&t);
}
__device__ __forceinline__ void split1h(float v, fp16& h, fp16& l) {
    h = __float2half(v);
    l = __float2half(v - __half2float(h));
}

#define LDSM4(r, addr) \
    asm volatile("ldmatrix.sync.aligned.m8n8.x4.shared.b16 {%0,%1,%2,%3}, [%4];" \
        : "=r"((r)[0]), "=r"((r)[1]), "=r"((r)[2]), "=r"((r)[3]) : "r"(addr))
#define LDSM4T(r, addr) \
    asm volatile("ldmatrix.sync.aligned.m8n8.x4.trans.shared.b16 {%0,%1,%2,%3}, [%4];" \
        : "=r"((r)[0]), "=r"((r)[1]), "=r"((r)[2]), "=r"((r)[3]) : "r"(addr))
#define MMA_F16(acc, a, b0, b1) \
    asm volatile("mma.sync.aligned.m16n8k16.row.col.f32.f16.f16.f32 " \
        "{%0,%1,%2,%3}, {%4,%5,%6,%7}, {%8,%9}, {%0,%1,%2,%3};" \
        : "+f"((acc)[0]), "+f"((acc)[1]), "+f"((acc)[2]), "+f"((acc)[3]) \
        : "r"((a)[0]), "r"((a)[1]), "r"((a)[2]), "r"((a)[3]), "r"(b0), "r"(b1))
#define CP16(dst, src) \
    asm volatile("cp.async.cg.shared.global [%0], [%1], 16;\n" :: "r"(dst), "l"(src) : "memory")
#define CP_COMMIT() asm volatile("cp.async.commit_group;\n" ::: "memory")
#define CP_WAIT(n)  asm volatile("cp.async.wait_group %0;\n" :: "n"(n) : "memory")

// ---------------- fp32 -> fp16 hi/lo split ----------------
__global__ void splith_kernel(const float* __restrict__ in,
                              fp16* __restrict__ hi, fp16* __restrict__ lo, int n4) {
    int i = blockIdx.x * blockDim.x + threadIdx.x;
    if (i >= n4) return;
    float4 v = ((const float4*)in)[i];
    float vv[4] = {v.x, v.y, v.z, v.w};
    fp16 h[4], l[4];
    #pragma unroll
    for (int j = 0; j < 4; j++) split1h(vv[j], h[j], l[j]);
    ((uint2*)hi)[i] = make_uint2(pack2h(h[0],h[1]), pack2h(h[2],h[3]));
    ((uint2*)lo)[i] = make_uint2(pack2h(l[0],l[1]), pack2h(l[2],l[3]));
}

// ---- strided fp16 split: in[K,Nin] -> planes[K,Nout] at column cOff ----
__global__ void splitwh_kernel(const float* __restrict__ in,
                               fp16* __restrict__ oh, fp16* __restrict__ ol,
                               int Nin, int Nout, int cOff, int n4) {
    int i = blockIdx.x * blockDim.x + threadIdx.x;
    if (i >= n4) return;
    int rc4 = Nin >> 2;
    int r = i / rc4, c4 = i - r * rc4;
    float4 v = ((const float4*)in)[i];
    float vv[4] = {v.x, v.y, v.z, v.w};
    fp16 h[4], l[4];
    #pragma unroll
    for (int q = 0; q < 4; q++) split1h(vv[q], h[q], l[q]);
    size_t oi = ((size_t)r * Nout + cOff) / 4 + c4;
    ((uint2*)oh)[oi] = make_uint2(pack2h(h[0],h[1]), pack2h(h[2],h[3]));
    ((uint2*)ol)[oi] = make_uint2(pack2h(l[0],l[1]), pack2h(l[2],l[3]));
}

// ---- gate/up interleaved fp16 split ----
__global__ void splitguh_kernel(const float* __restrict__ wg,
                                const float* __restrict__ wu,
                                fp16* __restrict__ oh, fp16* __restrict__ ol, int n4) {
    int i = blockIdx.x * blockDim.x + threadIdx.x;
    if (i >= n4) return;
    float4 gv = ((const float4*)wg)[i];
    float4 uv = ((const float4*)wu)[i];
    float gg[4] = {gv.x, gv.y, gv.z, gv.w};
    float uu[4] = {uv.x, uv.y, uv.z, uv.w};
    fp16 ghh[4], gll[4], uhh[4], ull[4];
    #pragma unroll
    for (int q = 0; q < 4; q++) { split1h(gg[q], ghh[q], gll[q]); split1h(uu[q], uhh[q], ull[q]); }
    uint4 hO, lO;
    hO.x = pack2h(ghh[0], uhh[0]); hO.y = pack2h(ghh[1], uhh[1]);
    hO.z = pack2h(ghh[2], uhh[2]); hO.w = pack2h(ghh[3], uhh[3]);
    lO.x = pack2h(gll[0], ull[0]); lO.y = pack2h(gll[1], ull[1]);
    lO.z = pack2h(gll[2], ull[2]); lO.w = pack2h(gll[3], ull[3]);
    ((uint4*)oh)[i] = hO;
    ((uint4*)ol)[i] = lO;
}

// ---------------- idx detection + embed ----------------
__global__ void detect_idx_kernel(const int* idx) {
    __shared__ int ok;
    if (threadIdx.x == 0) ok = 1;
    __syncthreads();
    int bad = 0;
    for (int i = threadIdx.x; i < T_/2; i += blockDim.x)
        if (idx[2*i + 1] != 0) bad = 1;
    if (bad) atomicAnd(&ok, 0);
    __syncthreads();
    if (threadIdx.x == 0) g_is64 = ok;
}
__global__ void embed_kernel(const void* idx, const float* __restrict__ emb) {
    int t = blockIdx.x;
    int tok = g_is64 ? (int)((const long long*)idx)[t] : ((const int*)idx)[t];
    ((float4*)(g_x + (size_t)t * D_))[threadIdx.x] =
        ((const float4*)(emb + (size_t)tok * D_))[threadIdx.x];
}

// ---------------- RMSNorm -> fp16 single plane --------------------------
__global__ void rmsnorm_h_kernel(const float* __restrict__ x,
                                 const float* __restrict__ w,
                                 fp16* __restrict__ o) {
    int t = blockIdx.x;
    __shared__ float red[8];
    float4 v = ((const float4*)(x + (size_t)t * D_))[threadIdx.x];
    float ss = v.x*v.x + v.y*v.y + v.z*v.z + v.w*v.w;
    #pragma unroll
    for (int off = 16; off > 0; off >>= 1) ss += __shfl_xor_sync(0xffffffffu, ss, off);
    if ((threadIdx.x & 31) == 0) red[threadIdx.x >> 5] = ss;
    __syncthreads();
    if (threadIdx.x < 8) {
        float s = red[threadIdx.x];
        #pragma unroll
        for (int off = 4; off > 0; off >>= 1) s += __shfl_xor_sync(0xffu, s, off);
        if (threadIdx.x == 0) red[0] = s;
    }
    __syncthreads();
    float inv = rsqrtf(red[0] * (1.0f / D_) + EPS_);
    float4 wv = ((const float4*)w)[threadIdx.x];
    fp16 h0 = __float2half(v.x*inv*wv.x), h1 = __float2half(v.y*inv*wv.y);
    fp16 h2 = __float2half(v.z*inv*wv.z), h3 = __float2half(v.w*inv*wv.w);
    ((uint2*)(o + (size_t)t*D_))[threadIdx.x] = make_uint2(pack2h(h0,h1), pack2h(h2,h3));
}

// ------- merged qkv postprocess: rope(q), rope(k 2-plane), v split ------
__global__ void __launch_bounds__(512)
qkvpost_kernel(const float* __restrict__ x,
               fp16* __restrict__ q,
               fp16* __restrict__ kh, fp16* __restrict__ kl,
               fp16* __restrict__ vh, fp16* __restrict__ vl) {
    int t   = blockIdx.x;
    int pos = t % S_;
    int tid = threadIdx.x;
    int j   = tid & 31;
    int h   = tid >> 5;          // 0..15
    float invf = powf(500000.0f, -(float)(2 * j) / (float)HD_);
    float ang = (float)pos * invf;
    float s, c;
    sincosf(ang, &s, &c);

    // q: all 16 heads
    {
        const float* p = x + (size_t)t * QKV_ + h * HD_;
        size_t ob = (size_t)t * D_ + h * HD_;
        float a = p[j], b = p[j + 32];
        q[ob + j]      = __float2half((a * c - b * s) * SCALE_);
        q[ob + j + 32] = __float2half((b * c + a * s) * SCALE_);
    }
    // k: heads 0..3 handled by tid < 128
    if (tid < 128) {
        const float* p = x + (size_t)t * QKV_ + 1024 + h * HD_;
        size_t ob = (size_t)t * (KVH_*HD_) + h * HD_;
        float a = p[j], b = p[j + 32];
        float r0 = a * c - b * s;
        float r1 = b * c + a * s;
        fp16 h0, l0, h1, l1;
        split1h(r0, h0, l0); split1h(r1, h1, l1);
        kh[ob + j] = h0;       kl[ob + j] = l0;
        kh[ob + j + 32] = h1;  kl[ob + j + 32] = l1;
    }
    // v: 256 floats, tid < 64 each does float4
    if (tid < 64) {
        float4 v = *(const float4*)(x + (size_t)t*QKV_ + 1280 + tid*4);
        float vv[4] = {v.x, v.y, v.z, v.w};
        fp16 hh[4], ll[4];
        #pragma unroll
        for (int jq = 0; jq < 4; jq++) split1h(vv[jq], hh[jq], ll[jq]);
        ((uint2*)(vh + (size_t)t*256))[tid] = make_uint2(pack2h(hh[0],hh[1]), pack2h(hh[2],hh[3]));
        ((uint2*)(vl + (size_t)t*256))[tid] = make_uint2(pack2h(ll[0],ll[1]), pack2h(ll[2],ll[3]));
    }
}

// ======== fp16 2-MMA GEMM: A 1-plane, B 2-plane, 3-stage cp.async =======
// Grid: (N/BN, M/BM) — N fastest (empirically correct order on this chip).
// EPI 0: fp32 out (+opt Res).  EPI 1: silu(gate)*up from interleaved cols,
//        fp16 1-plane out of width N/2.
#define BM_  128
#define BN_  128
#define BKK_ 32
#define AST_ 40
#define BST_ 136
#define ASZ_ (BM_*AST_)
#define BSZ_ (BKK_*BST_)
#define STGE_ (ASZ_ + 2*BSZ_)          // elems per stage: A, Bh, Bl
#define NST_  3
#define HG_SMEM (NST_ * STGE_ * 2)

template <int EPI>
__global__ void __launch_bounds__(256)
hgemm_kernel(const fp16* __restrict__ Ag,
             const fp16* __restrict__ Bhg, const fp16* __restrict__ Blg,
             const float* __restrict__ Res, float* __restrict__ C,
             fp16* __restrict__ O, int M, int N, int K) {
    extern __shared__ fp16 hsm[];

    const int tid  = threadIdx.x;
    const int lane = tid & 31, warp = tid >> 5;
    const int warpM = warp >> 1, warpN = warp & 1;
    const int bx = blockIdx.x;   // N-tile (fastest)
    const int by = blockIdx.y;   // M-tile

    const fp16* Ab  = Ag  + (size_t)by * BM_ * K;
    const fp16* Bhb = Bhg + (size_t)bx * BN_;
    const fp16* Blb = Blg + (size_t)bx * BN_;

    const uint32_t uS = (uint32_t)__cvta_generic_to_shared(hsm);

    const int ar = tid >> 2, ac = (tid & 3) * 8;
    const int br = tid >> 4, bc = (tid & 15) * 8;

    auto load_stage = [&](int st, int k0) {
        uint32_t base = uS + (uint32_t)(st * STGE_ * 2);
        #pragma unroll
        for (int p = 0; p < 2; p++) {
            int r = ar + p*64;
            CP16(base + (uint32_t)((r*AST_ + ac) * 2), Ab + (size_t)r*K + k0 + ac);
        }
        #pragma unroll
        for (int p = 0; p < 2; p++) {
            int r = br + p*16;
            uint32_t d = (uint32_t)((r*BST_ + bc) * 2);
            CP16(base + ASZ_*2 + d,             Bhb + (size_t)(k0 + r)*N + bc);
            CP16(base + (ASZ_ + BSZ_)*2 + d,    Blb + (size_t)(k0 + r)*N + bc);
        }
    };

    float acc[2][8][4];
    #pragma unroll
    for (int i = 0; i < 2; i++)
        #pragma unroll
        for (int j = 0; j < 8; j++)
            #pragma unroll
            for (int q = 0; q < 4; q++) acc[i][j][q] = 0.f;

    const int arow = warpM*32 + (lane & 15);
    const int acol = (lane >> 4) * 8;
    const int brow = (lane & 15);
    const int bcol = warpN*64 + (lane >> 4) * 8;

    const int kIters = K / BKK_;
    load_stage(0, 0);
    CP_COMMIT();
    if (kIters > 1) { load_stage(1, BKK_); CP_COMMIT(); }

    for (int it = 0; it < kIters; ++it) {
        if (it + 2 < kIters) {
            load_stage((it + 2) % NST_, (it + 2) * BKK_);
            CP_COMMIT();
            CP_WAIT(2);
        } else if (it + 1 < kIters) {
            CP_WAIT(1);
        } else {
            CP_WAIT(0);
        }
        __syncthreads();
        const uint32_t sb = uS + (uint32_t)((it % NST_) * STGE_ * 2);
        const uint32_t aA = sb;
        const uint32_t bH = sb + (uint32_t)(ASZ_*2);
        const uint32_t bL = sb + (uint32_t)((ASZ_ + BSZ_)*2);
        #pragma unroll
        for (int kk = 0; kk < BKK_; kk += 16) {
            uint32_t a4[2][4];
            #pragma unroll
            for (int mt = 0; mt < 2; mt++) {
                uint32_t off = (uint32_t)(((arow + mt*16)*AST_ + kk + acol) * 2);
                LDSM4(a4[mt], aA + off);
            }
            #pragma unroll
            for (int pr = 0; pr < 4; pr++) {
                uint32_t off = (uint32_t)(((brow + kk)*BST_ + bcol + pr*16) * 2);
                uint32_t bh[4], bl[4];
                LDSM4T(bh, bH + off);
                LDSM4T(bl, bL + off);
                #pragma unroll
                for (int mt = 0; mt < 2; mt++) {
                    #pragma unroll
                    for (int h2 = 0; h2 < 2; h2++) {
                        int nt = pr*2 + h2;
                        MMA_F16(acc[mt][nt], a4[mt], bh[h2*2], bh[h2*2+1]);
                        MMA_F16(acc[mt][nt], a4[mt], bl[h2*2], bl[h2*2+1]);
                    }
                }
            }
        }
        __syncthreads();
    }

    const int g = lane >> 2, tg = lane & 3;
    if (EPI == 0) {
        #pragma unroll
        for (int mt = 0; mt < 2; mt++) {
            #pragma unroll
            for (int nt = 0; nt < 8; nt++) {
                size_t r0 = (size_t)by*BM_ + warpM*32 + mt*16 + g;
                size_t c  = (size_t)bx*BN_ + warpN*64 + nt*8 + tg*2;
                float2 v0 = make_float2(acc[mt][nt][0], acc[mt][nt][1]);
                float2 v1 = make_float2(acc[mt][nt][2], acc[mt][nt][3]);
                if (Res) {
                    float2 q0 = *(const float2*)(Res + r0*N + c);
                    float2 q1 = *(const float2*)(Res + (r0+8)*N + c);
                    v0.x += q0.x; v0.y += q0.y; v1.x += q1.x; v1.y += q1.y;
                }
                *(float2*)(C + r0*N + c)     = v0;
                *(float2*)(C + (r0+8)*N + c) = v1;
            }
        }
    } else {
        // silu(gate)*up epilogue: cols (c, c+1) = (gate_j, up_j), j = c/2.
        const int NO = N >> 1;
        #pragma unroll
        for (int mt = 0; mt < 2; mt++) {
            #pragma unroll
            for (int nt = 0; nt < 8; nt++) {
                size_t r0 = (size_t)by*BM_ + warpM*32 + mt*16 + g;
                size_t j  = (size_t)bx*(BN_/2) + warpN*32 + nt*4 + tg;
                float gate0 = acc[mt][nt][0], up0 = acc[mt][nt][1];
                float gate1 = acc[mt][nt][2], up1 = acc[mt][nt][3];
                float v0 = gate0 / (1.f + __expf(-gate0)) * up0;
                float v1 = gate1 / (1.f + __expf(-gate1)) * up1;
                O[r0*NO + j]     = __float2half(v0);
                O[(r0+8)*NO + j] = __float2half(v1);
            }
        }
    }
}

// ================= fp16 flash attention (2-MMA) =========================
// Q 1-plane (pre-scaled), K/V 2-plane, P 1-plane, ctx 1-plane out.
#define FST 72
#define FQSZ (64*FST)
#define FL_SMEM (5 * FQSZ * 2)

__global__ void __launch_bounds__(128)
flash_h_kernel(const fp16* __restrict__ qg,
               const fp16* __restrict__ kh, const fp16* __restrict__ kl,
               const fp16* __restrict__ vh, const fp16* __restrict__ vl,
               fp16* __restrict__ cg) {
    extern __shared__ fp16 fsm[];
    fp16* sQ  = fsm;
    fp16* sKh = sQ  + FQSZ;
    fp16* sKl = sKh + FQSZ;
    fp16* sVh = sKl + FQSZ;
    fp16* sVl = sVh + FQSZ;

    const int q0  = blockIdx.x * 64;
    const int h   = blockIdx.y;
    const int b   = blockIdx.z;
    const int kvh = h / REP_;
    const int tid = threadIdx.x;
    const int lane = tid & 31, warp = tid >> 5;
    const int g = lane >> 2, tg = lane & 3;

    for (int li = tid; li < 512; li += 128) {
        int r = li >> 3, c8 = (li & 7) * 8;
        size_t src = ((size_t)(b * S_ + q0 + r) * D_ + h * HD_ + c8);
        *(uint4*)&sQ[r*FST + c8] = *(const uint4*)(qg + src);
    }

    float mrow[2] = {-INFINITY, -INFINITY};
    float lrow[2] = {0.f, 0.f};
    float o[8][4] = {};

    const uint32_t uQ  = (uint32_t)__cvta_generic_to_shared(sQ);
    const uint32_t uKh = (uint32_t)__cvta_generic_to_shared(sKh);
    const uint32_t uKl = (uint32_t)__cvta_generic_to_shared(sKl);
    const uint32_t uVh = (uint32_t)__cvta_generic_to_shared(sVh);
    const uint32_t uVl = (uint32_t)__cvta_generic_to_shared(sVl);
    const int fr = (lane & 15);
    const int fc = (lane >> 4) * 8;

    const int ntiles = q0 / 64 + 1;
    for (int tI = 0; tI < ntiles; tI++) {
        int kv0 = tI * 64;
        __syncthreads();
        for (int li = tid; li < 512; li += 128) {
            int r = li >> 3, c8 = (li & 7) * 8;
            size_t src = ((size_t)(b * S_ + kv0 + r) * (KVH_*HD_) + kvh * HD_ + c8);
            *(uint4*)&sKh[r*FST + c8] = *(const uint4*)(kh + src);
            *(uint4*)&sKl[r*FST + c8] = *(const uint4*)(kl + src);
            *(uint4*)&sVh[r*FST + c8] = *(const uint4*)(vh + src);
            *(uint4*)&sVl[r*FST + c8] = *(const uint4*)(vl + src);
        }
        __syncthreads();

        // S = Q K^T : 2 MMAs (q·kh + q·kl)
        float s[8][4] = {};
        #pragma unroll
        for (int kk = 0; kk < 64; kk += 16) {
            uint32_t aq[4];
            uint32_t qoff = (uint32_t)(((warp*16 + fr)*FST + kk + fc) * 2);
            LDSM4(aq, uQ + qoff);
            #pragma unroll
            for (int nb = 0; nb < 4; nb++) {
                uint32_t koff = (uint32_t)(((nb*16 + fr)*FST + kk + fc) * 2);
                uint32_t k4h[4], k4l[4];
                LDSM4(k4h, uKh + koff);
                LDSM4(k4l, uKl + koff);
                MMA_F16(s[nb*2],   aq, k4h[0], k4h[2]);
                MMA_F16(s[nb*2],   aq, k4l[0], k4l[2]);
                MMA_F16(s[nb*2+1], aq, k4h[1], k4h[3]);
                MMA_F16(s[nb*2+1], aq, k4l[1], k4l[3]);
            }
        }

        if (tI == ntiles - 1) {
            #pragma unroll
            for (int nt = 0; nt < 8; nt++) {
                int col = kv0 + nt*8 + tg*2;
                int r0g = q0 + warp*16 + g;
                if (col     > r0g)   s[nt][0] = -INFINITY;
                if (col + 1 > r0g)   s[nt][1] = -INFINITY;
                if (col     > r0g+8) s[nt][2] = -INFINITY;
                if (col + 1 > r0g+8) s[nt][3] = -INFINITY;
            }
        }

        #pragma unroll
        for (int qi = 0; qi < 2; qi++) {
            float mx = -INFINITY;
            #pragma unroll
            for (int nt = 0; nt < 8; nt++)
                mx = fmaxf(mx, fmaxf(s[nt][qi*2], s[nt][qi*2+1]));
            mx = fmaxf(mx, __shfl_xor_sync(0xffffffffu, mx, 1));
            mx = fmaxf(mx, __shfl_xor_sync(0xffffffffu, mx, 2));
            float mnew = fmaxf(mrow[qi], mx);
            float scale = __expf(mrow[qi] - mnew);
            mrow[qi] = mnew;
            float sum = 0.f;
            #pragma unroll
            for (int nt = 0; nt < 8; nt++) {
                float p0 = __expf(s[nt][qi*2]   - mnew);
                float p1 = __expf(s[nt][qi*2+1] - mnew);
                s[nt][qi*2] = p0; s[nt][qi*2+1] = p1;
                sum += p0 + p1;
            }
            sum += __shfl_xor_sync(0xffffffffu, sum, 1);
            sum += __shfl_xor_sync(0xffffffffu, sum, 2);
            lrow[qi] = lrow[qi]*scale + sum;
            #pragma unroll
            for (int nt = 0; nt < 8; nt++) {
                o[nt][qi*2]   *= scale;
                o[nt][qi*2+1] *= scale;
            }
        }

        // O += P V : 2 MMAs (p·vh + p·vl); P packed fp16 1-plane
        #pragma unroll
        for (int ks = 0; ks < 4; ks++) {
            const float* s0 = s[2*ks];
            const float* s1 = s[2*ks+1];
            uint32_t ph[4];
            ph[0] = pack2h(__float2half(s0[0]), __float2half(s0[1]));
            ph[1] = pack2h(__float2half(s0[2]), __float2half(s0[3]));
            ph[2] = pack2h(__float2half(s1[0]), __float2half(s1[1]));
            ph[3] = pack2h(__float2half(s1[2]), __float2half(s1[3]));
            #pragma unroll
            for (int nb = 0; nb < 4; nb++) {
                uint32_t voff = (uint32_t)(((ks*16 + fr)*FST + nb*16 + fc) * 2);
                uint32_t v4h[4], v4l[4];
                LDSM4T(v4h, uVh + voff);
                LDSM4T(v4l, uVl + voff);
                MMA_F16(o[nb*2],   ph, v4h[0], v4h[1]);
                MMA_F16(o[nb*2],   ph, v4l[0], v4l[1]);
                MMA_F16(o[nb*2+1], ph, v4h[2], v4h[3]);
                MMA_F16(o[nb*2+1], ph, v4l[2], v4l[3]);
            }
        }
    }

    #pragma unroll
    for (int qi = 0; qi < 2; qi++) {
        float inv = 1.0f / lrow[qi];
        int r = q0 + warp*16 + g + qi*8;
        size_t base = (size_t)(b * S_ + r) * D_ + h * HD_;
        #pragma unroll
        for (int nt = 0; nt < 8; nt++) {
            int c = nt*8 + tg*2;
            *(uint32_t*)(cg + base + c) =
                pack2h(__float2half(o[nt][qi*2] * inv),
                       __float2half(o[nt][qi*2+1] * inv));
        }
    }
}

// ---------------- host orchestration ----------------
extern "C" void kernel_launch(void* const* d_in, const int* in_sizes, int n_in,
                              void* d_out, int out_size) {
    const void*  idx    = d_in[0];
    const float* emb    = (const float*)d_in[1];
    const float* wq     = (const float*)d_in[2];
    const float* wk     = (const float*)d_in[3];
    const float* wv     = (const float*)d_in[4];
    const float* wo     = (const float*)d_in[5];
    const float* wgate  = (const float*)d_in[6];
    const float* wup    = (const float*)d_in[7];
    const float* wdown  = (const float*)d_in[8];
    const float* na     = (const float*)d_in[9];
    const float* nf     = (const float*)d_in[10];
    const float* nfin   = (const float*)d_in[11];
    const float* wout   = (const float*)d_in[12];

    float *x, *qkv;
    cudaGetSymbolAddress((void**)&x,   g_x);
    cudaGetSymbolAddress((void**)&qkv, g_qkv);

    fp16 *nH, *qH, *kh, *kl, *vh, *vl, *cH, *gH;
    cudaGetSymbolAddress((void**)&nH, g_nH);
    cudaGetSymbolAddress((void**)&qH, g_qH);
    cudaGetSymbolAddress((void**)&kh, g_kh); cudaGetSymbolAddress((void**)&kl, g_kl);
    cudaGetSymbolAddress((void**)&vh, g_vh); cudaGetSymbolAddress((void**)&vl, g_vl);
    cudaGetSymbolAddress((void**)&cH, g_cH);
    cudaGetSymbolAddress((void**)&gH, g_gH);

    fp16 *wqkvH_h,*wqkvH_l,*woH_h,*woH_l,*wguH_h,*wguH_l,*wdH_h,*wdH_l,*woutH_h,*woutH_l;
    cudaGetSymbolAddress((void**)&wqkvH_h, g_wqkvH_h); cudaGetSymbolAddress((void**)&wqkvH_l, g_wqkvH_l);
    cudaGetSymbolAddress((void**)&woH_h,  g_woH_h);   cudaGetSymbolAddress((void**)&woH_l,  g_woH_l);
    cudaGetSymbolAddress((void**)&wguH_h, g_wguH_h);  cudaGetSymbolAddress((void**)&wguH_l, g_wguH_l);
    cudaGetSymbolAddress((void**)&wdH_h,  g_wdH_h);   cudaGetSymbolAddress((void**)&wdH_l,  g_wdH_l);
    cudaGetSymbolAddress((void**)&woutH_h,g_woutH_h); cudaGetSymbolAddress((void**)&woutH_l,g_woutH_l);

    cudaFuncSetAttribute(hgemm_kernel<0>,
                         cudaFuncAttributeMaxDynamicSharedMemorySize, HG_SMEM);
    cudaFuncSetAttribute(hgemm_kernel<1>,
                         cudaFuncAttributeMaxDynamicSharedMemorySize, HG_SMEM);
    cudaFuncSetAttribute(flash_h_kernel,
                         cudaFuncAttributeMaxDynamicSharedMemorySize, FL_SMEM);

    // weight splits (all fp16 2-plane)
    for (int l = 0; l < L_; l++) {
        size_t qo = (size_t)l * D_ * QKV_;
        {
            int n4 = D_ * D_ / 4;
            splitwh_kernel<<<(n4 + 255) / 256, 256>>>(
                wq + (size_t)l*D_*D_, wqkvH_h + qo, wqkvH_l + qo, D_, QKV_, 0, n4);
        }
        {
            int n4 = D_ * 256 / 4;
            splitwh_kernel<<<(n4 + 255) / 256, 256>>>(
                wk + (size_t)l*D_*256, wqkvH_h + qo, wqkvH_l + qo, 256, QKV_, 1024, n4);
            splitwh_kernel<<<(n4 + 255) / 256, 256>>>(
                wv + (size_t)l*D_*256, wqkvH_h + qo, wqkvH_l + qo, 256, QKV_, 1280, n4);
        }
        {
            int n4 = D_ * D_ / 4;
            splith_kernel<<<(n4 + 255) / 256, 256>>>(
                wo + (size_t)l*D_*D_, woH_h + (size_t)l*D_*D_, woH_l + (size_t)l*D_*D_, n4);
        }
        size_t go = (size_t)l * D_ * GU_;
        {
            int n4 = D_ * F_ / 4;
            splitguh_kernel<<<(n4 + 255) / 256, 256>>>(
                wgate + (size_t)l*D_*F_, wup + (size_t)l*D_*F_,
                wguH_h + go, wguH_l + go, n4);
        }
        {
            int n4 = F_ * D_ / 4;
            splith_kernel<<<(n4 + 255) / 256, 256>>>(
                wdown + (size_t)l*F_*D_, wdH_h + (size_t)l*F_*D_,
                wdH_l + (size_t)l*F_*D_, n4);
        }
    }
    {
        int n4 = (int)((size_t)D_*V_/4);
        splith_kernel<<<(n4 + 255) / 256, 256>>>(wout, woutH_h, woutH_l, n4);
    }

    detect_idx_kernel<<<1, 256>>>((const int*)idx);
    embed_kernel<<<T_, 256>>>(idx, emb);

    for (int l = 0; l < L_; l++) {
        size_t qo = (size_t)l * D_ * QKV_;
        size_t go = (size_t)l * D_ * GU_;
        rmsnorm_h_kernel<<<T_, 256>>>(x, na + (size_t)l * D_, nH);
        {   // QKV   (grid: N fastest — proven order)
            dim3 grid(QKV_ / BN_, T_ / BM_);
            hgemm_kernel<0><<<grid, 256, HG_SMEM>>>(nH, wqkvH_h + qo, wqkvH_l + qo,
                                                    nullptr, qkv, nullptr, T_, QKV_, D_);
        }
        qkvpost_kernel<<<T_, 512>>>(qkv, qH, kh, kl, vh, vl);
        flash_h_kernel<<<dim3(S_/64, H_, B_), 128, FL_SMEM>>>(qH, kh, kl, vh, vl, cH);
        {   // wo + residual
            dim3 grid(D_ / BN_, T_ / BM_);
            hgemm_kernel<0><<<grid, 256, HG_SMEM>>>(cH, woH_h + (size_t)l*D_*D_,
                                                    woH_l + (size_t)l*D_*D_,
                                                    x, x, nullptr, T_, D_, D_);
        }
        rmsnorm_h_kernel<<<T_, 256>>>(x, nf + (size_t)l * D_, nH);
        {   // GU with fused silu
            dim3 grid(GU_ / BN_, T_ / BM_);
            hgemm_kernel<1><<<grid, 256, HG_SMEM>>>(nH, wguH_h + go, wguH_l + go,
                                                    nullptr, nullptr, gH, T_, GU_, D_);
        }
        {   // wdown + residual
            dim3 grid(D_ / BN_, T_ / BM_);
            hgemm_kernel<0><<<grid, 256, HG_SMEM>>>(gH, wdH_h + (size_t)l*F_*D_,
                                                    wdH_l + (size_t)l*F_*D_,
                                                    x, x, nullptr, T_, D_, F_);
        }
    }

    rmsnorm_h_kernel<<<T_, 256>>>(x, nfin, nH);
    {   // vocab projection (grid: N fastest)
        dim3 grid(V_ / BN_, T_ / BM_);
        hgemm_kernel<0><<<grid, 256, HG_SMEM>>>(nH, woutH_h, woutH_l,
                                                nullptr, (float*)d_out, nullptr,
                                                T_, V_, D_);
    }
}